// round 1
// baseline (speedup 1.0000x reference)
#include <cuda_runtime.h>

// MetaUpscale: x (2,64,128,128) f32, lw (256,256,576,3) f32, scale=2
// out (2,3,256,256) f32
// out[n,ch,oh,ow] = sum_{c9} patch[n, oh/2, ow/2, c9] * lw[oh,ow,c9,ch]
// patch[n,hh,ww,c9] = x[n, c, hh+kh-1, ww+kw-1] (zero pad), c9 = c*9+kh*3+kw

#define HH_  128
#define WW_  128
#define CC_  64
#define C9_  576
#define LWPIX 1728   // C9*3 floats per output pixel
#define OHW  256

__global__ __launch_bounds__(256)
void meta_upscale_kernel(const float* __restrict__ x,
                         const float* __restrict__ lw,
                         float* __restrict__ out)
{
    // prep[pix][batch][e] = patch[batch, hh, ww0+pix, e/3]  (value replicated x3,
    // so prep is index-aligned with the lw (c9,ch) interleave)
    __shared__ float prep[2][2][LWPIX];

    const int bid = blockIdx.x;        // 8192 blocks = 128 hh rows x 64 col-pairs
    const int hh  = bid >> 6;
    const int wp  = bid & 63;
    const int ww0 = wp * 2;

    const int tid = threadIdx.x;

    // ---------------- build prep (both input pixels, both batches) ------------
    for (int idx = tid; idx < 2 * C9_; idx += 256) {
        const int pix = idx / C9_;
        const int c9  = idx - pix * C9_;
        const int c   = c9 / 9;
        const int r9  = c9 - c * 9;
        const int kh  = r9 / 3;
        const int kw  = r9 - kh * 3;
        const int y   = hh + kh - 1;
        const int xc  = ww0 + pix + kw - 1;
        float v0 = 0.0f, v1 = 0.0f;
        if ((unsigned)y < HH_ && (unsigned)xc < WW_) {
            const int off = (c * HH_ + y) * WW_ + xc;
            v0 = __ldg(x + off);
            v1 = __ldg(x + CC_ * HH_ * WW_ + off);
        }
        float* p0 = &prep[pix][0][3 * c9];
        float* p1 = &prep[pix][1][3 * c9];
        p0[0] = v0; p0[1] = v0; p0[2] = v0;
        p1[0] = v1; p1[1] = v1; p1[2] = v1;
    }
    __syncthreads();

    // ---------------- main loop: one warp per output pixel --------------------
    const int w    = tid >> 5;
    const int lane = tid & 31;
    const int pix  = w >> 2;           // which input pixel of the pair
    const int sub  = w & 3;            // subpixel (si,sj)
    const int si   = sub >> 1;
    const int sj   = sub & 1;
    const int oh   = 2 * hh + si;
    const int ow   = 2 * (ww0 + pix) + sj;

    const float2* __restrict__ lw2 =
        (const float2*)(lw + (size_t)(oh * OHW + ow) * LWPIX);
    const float2* __restrict__ pr0 = (const float2*)&prep[pix][0][0];
    const float2* __restrict__ pr1 = (const float2*)&prep[pix][1][0];

    // acc[m] holds channel (2*lane + m) % 3  (phase-rotated accumulation:
    // element e has channel e%3; e = 2*(lane+32*i)+k  ->  m = (i+k) % 3,
    // compile-time since the loop is unrolled by a multiple of 3)
    float a0[3] = {0.f, 0.f, 0.f};     // batch 0
    float a1[3] = {0.f, 0.f, 0.f};     // batch 1

    #pragma unroll 9
    for (int i = 0; i < 27; i++) {     // 27*32 = 864 float2 = 1728 floats
        const int j  = lane + 32 * i;
        const float2 wv = __ldcs(&lw2[j]);   // streaming: no reuse of lw
        const float2 p0 = pr0[j];
        const float2 p1 = pr1[j];
        const int r  = i % 3;                // compile-time under unroll
        const int r1 = (r + 1) % 3;
        a0[r]  += wv.x * p0.x;
        a0[r1] += wv.y * p0.y;
        a1[r]  += wv.x * p1.x;
        a1[r1] += wv.y * p1.y;
    }

    // ------------- remap phase-accumulators to channel order ------------------
    // channel ch lives in acc[(ch - ph) mod 3], ph = (2*lane) % 3
    const int ph = (2 * lane) % 3;
    float c0_0 = (ph == 0) ? a0[0] : (ph == 1) ? a0[2] : a0[1];
    float c1_0 = (ph == 0) ? a0[1] : (ph == 1) ? a0[0] : a0[2];
    float c2_0 = (ph == 0) ? a0[2] : (ph == 1) ? a0[1] : a0[0];
    float c0_1 = (ph == 0) ? a1[0] : (ph == 1) ? a1[2] : a1[1];
    float c1_1 = (ph == 0) ? a1[1] : (ph == 1) ? a1[0] : a1[2];
    float c2_1 = (ph == 0) ? a1[2] : (ph == 1) ? a1[1] : a1[0];

    // ------------- warp butterfly reduction ----------------------------------
    #pragma unroll
    for (int d = 16; d > 0; d >>= 1) {
        c0_0 += __shfl_xor_sync(0xFFFFFFFFu, c0_0, d);
        c1_0 += __shfl_xor_sync(0xFFFFFFFFu, c1_0, d);
        c2_0 += __shfl_xor_sync(0xFFFFFFFFu, c2_0, d);
        c0_1 += __shfl_xor_sync(0xFFFFFFFFu, c0_1, d);
        c1_1 += __shfl_xor_sync(0xFFFFFFFFu, c1_1, d);
        c2_1 += __shfl_xor_sync(0xFFFFFFFFu, c2_1, d);
    }

    if (lane == 0) {
        // out[n][ch][oh][ow], shape (2,3,256,256)
        const int p = oh * OHW + ow;
        out[0 * 3 * OHW * OHW + 0 * OHW * OHW + p] = c0_0;
        out[0 * 3 * OHW * OHW + 1 * OHW * OHW + p] = c1_0;
        out[0 * 3 * OHW * OHW + 2 * OHW * OHW + p] = c2_0;
        out[1 * 3 * OHW * OHW + 0 * OHW * OHW + p] = c0_1;
        out[1 * 3 * OHW * OHW + 1 * OHW * OHW + p] = c1_1;
        out[1 * 3 * OHW * OHW + 2 * OHW * OHW + p] = c2_1;
    }
}

extern "C" void kernel_launch(void* const* d_in, const int* in_sizes, int n_in,
                              void* d_out, int out_size)
{
    const float* x  = (const float*)d_in[0];   // (2,64,128,128) f32
    const float* lw = (const float*)d_in[1];   // (256,256,576,3) f32
    float* out = (float*)d_out;                // (2,3,256,256) f32

    // 128 rows x 64 column-pairs, 256 threads (8 warps = 8 output pixels/block)
    meta_upscale_kernel<<<128 * 64, 256>>>(x, lw, out);
}

// round 3
// speedup vs baseline: 1.1784x; 1.1784x over previous
#include <cuda_runtime.h>

// MetaUpscale: x (2,64,128,128) f32, lw (256,256,576,3) f32, scale=2
// out (2,3,256,256) f32
// out[n,ch,oh,ow] = sum_{c9} patch[n, oh/2, ow/2, c9] * lw[oh,ow,c9,ch]
// patch[n,hh,ww,c9] = x[n, c, hh+kh-1, ww+kw-1] (zero pad), c9 = c*9+kh*3+kw
//
// R2 design: block = 256 threads = 8 warps; each warp owns ONE input pixel and
// streams the lw blocks of ALL FOUR of its output subpixels (they share the
// patch -> LDS traffic per DRAM byte drops 4x vs one-warp-per-subpixel).
// Patch stored non-replicated, batches interleaved: prepI[pix][c9] = {b0,b1}.

#define HH_   128
#define WW_   128
#define CC_   64
#define C9_   576
#define LWPIX 1728          // C9*3 floats per output pixel
#define OHW   256
#define PIX_PER_BLK 8

__global__ __launch_bounds__(256, 4)
void meta_upscale_kernel(const float* __restrict__ x,
                         const float* __restrict__ lw,
                         float* __restrict__ out)
{
    __shared__ float2 prepI[PIX_PER_BLK][C9_];   // {batch0, batch1} per c9

    const int bid = blockIdx.x;          // 2048 = 128 rows x 16 groups of 8 px
    const int hh  = bid >> 4;
    const int gw  = bid & 15;
    const int ww_base = gw * PIX_PER_BLK;

    const int tid = threadIdx.x;

    // ------------- build prepI: 8 pixels x 576 c9, both batches --------------
    for (int idx = tid; idx < PIX_PER_BLK * C9_; idx += 256) {
        const int wp = idx / C9_;
        const int c9 = idx - wp * C9_;
        const int c  = c9 / 9;
        const int r9 = c9 - c * 9;
        const int kh = r9 / 3;
        const int kw = r9 - kh * 3;
        const int y  = hh + kh - 1;
        const int xc = ww_base + wp + kw - 1;
        float v0 = 0.0f, v1 = 0.0f;
        if ((unsigned)y < HH_ && (unsigned)xc < WW_) {
            const int off = (c * HH_ + y) * WW_ + xc;
            v0 = __ldg(x + off);
            v1 = __ldg(x + CC_ * HH_ * WW_ + off);
        }
        prepI[wp][c9] = make_float2(v0, v1);
    }
    __syncthreads();

    // ------------- main loop: 1 warp = 1 input pixel, 4 lw streams -----------
    const int w    = tid >> 5;           // warp id = pixel index in group
    const int lane = tid & 31;
    const int ww   = ww_base + w;

    const int oh0 = 2 * hh;
    const int ow0 = 2 * ww;

    // four subpixel streams: (si,sj) = (0,0),(0,1),(1,0),(1,1)
    const float2* __restrict__ s0 = (const float2*)(lw + (size_t)(oh0 * OHW + ow0) * LWPIX);
    const float2* __restrict__ s1 = (const float2*)(lw + (size_t)(oh0 * OHW + ow0 + 1) * LWPIX);
    const float2* __restrict__ s2 = (const float2*)(lw + (size_t)((oh0 + 1) * OHW + ow0) * LWPIX);
    const float2* __restrict__ s3 = (const float2*)(lw + (size_t)((oh0 + 1) * OHW + ow0 + 1) * LWPIX);
    const float2* __restrict__ pr = &prepI[w][0];

    // acc[sub][batch][m]: element e has channel e%3 = (p + m)%3, p=(2*lane)%3,
    // m = (t+k)%3 with k = element offset inside the float2 (compile-time).
    float acc[4][2][3];
    #pragma unroll
    for (int a = 0; a < 4; a++)
        #pragma unroll
        for (int b = 0; b < 2; b++) {
            acc[a][b][0] = 0.f; acc[a][b][1] = 0.f; acc[a][b][2] = 0.f;
        }

    #pragma unroll 3
    for (int t = 0; t < 27; t++) {       // 27*32 float2 = 1728 floats per stream
        const int j   = lane + 32 * t;
        const int u   = 2 * j;
        const int c9a = u / 3;           // patch index of element 2j
        const int c9b = (u + 1) / 3;     // patch index of element 2j+1
        const float2 pa = pr[c9a];       // {b0, b1}
        const float2 pb = pr[c9b];

        const float2 w0 = __ldcs(&s0[j]);
        const float2 w1 = __ldcs(&s1[j]);
        const float2 w2 = __ldcs(&s2[j]);
        const float2 w3 = __ldcs(&s3[j]);

        const int m0 = t % 3;            // compile-time under unroll-by-3
        const int m1 = (t + 1) % 3;

        acc[0][0][m0] += w0.x * pa.x;  acc[0][1][m0] += w0.x * pa.y;
        acc[0][0][m1] += w0.y * pb.x;  acc[0][1][m1] += w0.y * pb.y;
        acc[1][0][m0] += w1.x * pa.x;  acc[1][1][m0] += w1.x * pa.y;
        acc[1][0][m1] += w1.y * pb.x;  acc[1][1][m1] += w1.y * pb.y;
        acc[2][0][m0] += w2.x * pa.x;  acc[2][1][m0] += w2.x * pa.y;
        acc[2][0][m1] += w2.y * pb.x;  acc[2][1][m1] += w2.y * pb.y;
        acc[3][0][m0] += w3.x * pa.x;  acc[3][1][m0] += w3.x * pa.y;
        acc[3][0][m1] += w3.y * pb.x;  acc[3][1][m1] += w3.y * pb.y;
    }

    // ------------- remap phase accumulators -> channel order -----------------
    // channel ch lives in acc[..][..][(ch - p) mod 3], p = (2*lane) % 3
    const int p = (2 * lane) % 3;
    float r[4][2][3];
    #pragma unroll
    for (int a = 0; a < 4; a++)
        #pragma unroll
        for (int b = 0; b < 2; b++) {
            // p=0: m=ch ; p=1: m=(ch+2)%3 ; p=2: m=(ch+1)%3
            r[a][b][0] = (p == 0) ? acc[a][b][0] : (p == 1) ? acc[a][b][2] : acc[a][b][1];
            r[a][b][1] = (p == 0) ? acc[a][b][1] : (p == 1) ? acc[a][b][0] : acc[a][b][2];
            r[a][b][2] = (p == 0) ? acc[a][b][2] : (p == 1) ? acc[a][b][1] : acc[a][b][0];
        }

    // ------------- warp butterfly reduction (24 values) ----------------------
    #pragma unroll
    for (int d = 16; d > 0; d >>= 1) {
        #pragma unroll
        for (int a = 0; a < 4; a++)
            #pragma unroll
            for (int b = 0; b < 2; b++) {
                r[a][b][0] += __shfl_xor_sync(0xFFFFFFFFu, r[a][b][0], d);
                r[a][b][1] += __shfl_xor_sync(0xFFFFFFFFu, r[a][b][1], d);
                r[a][b][2] += __shfl_xor_sync(0xFFFFFFFFu, r[a][b][2], d);
            }
    }

    if (lane == 0) {
        #pragma unroll
        for (int a = 0; a < 4; a++) {
            const int oh = oh0 + (a >> 1);
            const int ow = ow0 + (a & 1);
            const int pix = oh * OHW + ow;
            #pragma unroll
            for (int b = 0; b < 2; b++) {
                out[(b * 3 + 0) * OHW * OHW + pix] = r[a][b][0];
                out[(b * 3 + 1) * OHW * OHW + pix] = r[a][b][1];
                out[(b * 3 + 2) * OHW * OHW + pix] = r[a][b][2];
            }
        }
    }
}

extern "C" void kernel_launch(void* const* d_in, const int* in_sizes, int n_in,
                              void* d_out, int out_size)
{
    const float* x  = (const float*)d_in[0];   // (2,64,128,128) f32
    const float* lw = (const float*)d_in[1];   // (256,256,576,3) f32
    float* out = (float*)d_out;                // (2,3,256,256) f32

    // 128 rows x 16 groups of 8 pixels; 8 warps/block, 1 warp per input pixel
    meta_upscale_kernel<<<128 * 16, 256>>>(x, lw, out);
}

// round 4
// speedup vs baseline: 1.3347x; 1.1326x over previous
#include <cuda_runtime.h>

// MetaUpscale: x (2,64,128,128) f32, lw (256,256,576,3) f32, scale=2
// out (2,3,256,256) f32
// out[n,ch,oh,ow] = sum_{c9} patch[n, oh/2, ow/2, c9] * lw[oh,ow,c9,ch]
//
// R3: warp = one input pixel; streams its TWO contiguous lw row-segments
// (each 3456 floats = the two horizontally adjacent subpixels) as float4.
// 864 float4 / 32 lanes = 27 iterations exactly. Subpixel boundary falls at
// t=13, lane 16 (compile-time except one peeled iteration).

#define HH_   128
#define WW_   128
#define CC_   64
#define C9_   576
#define LWPIX 1728
#define OHW   256
#define PIX_PER_BLK 8

// Accumulate one float4 pair (rows A,B) into acc[row][S][batch][m].
// k0 -> pa, k1 -> q1, k2 -> q2, k3 -> pb ; slots m0..m2, k3 shares m0.
#define ACCUM(S)                                                         \
    do {                                                                 \
        acc[0][S][0][m0] += wa.x * pa.x;                                 \
        acc[0][S][0][m1] += wa.y * q1.x;                                 \
        acc[0][S][0][m2] += wa.z * q2.x;                                 \
        acc[0][S][0][m0] += wa.w * pb.x;                                 \
        acc[0][S][1][m0] += wa.x * pa.y;                                 \
        acc[0][S][1][m1] += wa.y * q1.y;                                 \
        acc[0][S][1][m2] += wa.z * q2.y;                                 \
        acc[0][S][1][m0] += wa.w * pb.y;                                 \
        acc[1][S][0][m0] += wb.x * pa.x;                                 \
        acc[1][S][0][m1] += wb.y * q1.x;                                 \
        acc[1][S][0][m2] += wb.z * q2.x;                                 \
        acc[1][S][0][m0] += wb.w * pb.x;                                 \
        acc[1][S][1][m0] += wb.x * pa.y;                                 \
        acc[1][S][1][m1] += wb.y * q1.y;                                 \
        acc[1][S][1][m2] += wb.z * q2.y;                                 \
        acc[1][S][1][m0] += wb.w * pb.y;                                 \
    } while (0)

__global__ __launch_bounds__(256, 3)
void meta_upscale_kernel(const float* __restrict__ x,
                         const float* __restrict__ lw,
                         float* __restrict__ out)
{
    __shared__ float2 prepI[PIX_PER_BLK][C9_];   // {batch0, batch1} per c9

    const int bid = blockIdx.x;          // 2048 = 128 rows x 16 groups of 8 px
    const int hh  = bid >> 4;
    const int gw  = bid & 15;
    const int ww_base = gw * PIX_PER_BLK;
    const int tid = threadIdx.x;

    // ------------- build prepI: 8 pixels x 576 c9, both batches --------------
    for (int idx = tid; idx < PIX_PER_BLK * C9_; idx += 256) {
        const int wp = idx / C9_;
        const int c9 = idx - wp * C9_;
        const int c  = c9 / 9;
        const int r9 = c9 - c * 9;
        const int kh = r9 / 3;
        const int kw = r9 - kh * 3;
        const int y  = hh + kh - 1;
        const int xc = ww_base + wp + kw - 1;
        float v0 = 0.0f, v1 = 0.0f;
        if ((unsigned)y < HH_ && (unsigned)xc < WW_) {
            const int off = (c * HH_ + y) * WW_ + xc;
            v0 = __ldg(x + off);
            v1 = __ldg(x + CC_ * HH_ * WW_ + off);
        }
        prepI[wp][c9] = make_float2(v0, v1);
    }
    __syncthreads();

    // ------------- main loop: warp streams 2 contiguous row segments ---------
    const int w    = tid >> 5;           // warp = pixel index in group
    const int lane = tid & 31;
    const int ww   = ww_base + w;
    const int oh0  = 2 * hh;
    const int ow0  = 2 * ww;

    const float4* __restrict__ rowA =
        (const float4*)(lw + (size_t)(oh0 * OHW + ow0) * LWPIX);       // 3456 f
    const float4* __restrict__ rowB =
        (const float4*)(lw + (size_t)((oh0 + 1) * OHW + ow0) * LWPIX); // 3456 f
    const float2* __restrict__ pr = &prepI[w][0];

    // acc[row(2)][sub(2)][batch(2)][m(3)]; elem channel = (lane%3 + m) % 3
    float acc[2][2][2][3];
    #pragma unroll
    for (int a = 0; a < 2; a++)
        #pragma unroll
        for (int s = 0; s < 2; s++)
            #pragma unroll
            for (int b = 0; b < 2; b++) {
                acc[a][s][b][0] = 0.f; acc[a][s][b][1] = 0.f; acc[a][s][b][2] = 0.f;
            }

    #pragma unroll
    for (int t = 0; t < 27; t++) {
        const int u = lane + 32 * t;               // float4 index in segment
        const float4 wa = __ldcs(&rowA[u]);
        const float4 wb = __ldcs(&rowB[u]);

        const int g   = 4 * u;                     // element index (0..3455)
        const int c9g = g / 3;                     // global patch index
        const int r   = g - 3 * c9g;               // g % 3 (per-lane runtime)

        // subpixel: g >= 1728  <=>  t>13, or t==13 && lane>=16
        int c9l;
        if (t < 13)       c9l = c9g;
        else if (t > 13)  c9l = c9g - 576;
        else              c9l = c9g - ((lane >= 16) ? 576 : 0);

        const float2 pa = pr[c9l];
        const float2 pb = pr[c9l + 1];
        const float2 q1 = (r >= 2) ? pb : pa;      // element k=1
        const float2 q2 = (r >= 1) ? pb : pa;      // element k=2

        const int m0 = (2 * t) % 3;                // compile-time (full unroll)
        const int m1 = (2 * t + 1) % 3;
        const int m2 = (2 * t + 2) % 3;

        if (t < 13)      { ACCUM(0); }
        else if (t > 13) { ACCUM(1); }
        else {
            if (lane < 16) { ACCUM(0); } else { ACCUM(1); }
        }
    }

    // ------------- remap phase accumulators -> channel order -----------------
    // channel ch lives at m = (ch - p0) mod 3, p0 = lane % 3
    const int p0 = lane % 3;
    float rr[2][2][2][3];
    #pragma unroll
    for (int a = 0; a < 2; a++)
        #pragma unroll
        for (int s = 0; s < 2; s++)
            #pragma unroll
            for (int b = 0; b < 2; b++) {
                rr[a][s][b][0] = (p0 == 0) ? acc[a][s][b][0] : (p0 == 1) ? acc[a][s][b][2] : acc[a][s][b][1];
                rr[a][s][b][1] = (p0 == 0) ? acc[a][s][b][1] : (p0 == 1) ? acc[a][s][b][0] : acc[a][s][b][2];
                rr[a][s][b][2] = (p0 == 0) ? acc[a][s][b][2] : (p0 == 1) ? acc[a][s][b][1] : acc[a][s][b][0];
            }

    // ------------- warp butterfly reduction (24 values) ----------------------
    #pragma unroll
    for (int d = 16; d > 0; d >>= 1) {
        #pragma unroll
        for (int a = 0; a < 2; a++)
            #pragma unroll
            for (int s = 0; s < 2; s++)
                #pragma unroll
                for (int b = 0; b < 2; b++) {
                    rr[a][s][b][0] += __shfl_xor_sync(0xFFFFFFFFu, rr[a][s][b][0], d);
                    rr[a][s][b][1] += __shfl_xor_sync(0xFFFFFFFFu, rr[a][s][b][1], d);
                    rr[a][s][b][2] += __shfl_xor_sync(0xFFFFFFFFu, rr[a][s][b][2], d);
                }
    }

    if (lane == 0) {
        #pragma unroll
        for (int a = 0; a < 2; a++) {
            const int oh = oh0 + a;
            #pragma unroll
            for (int s = 0; s < 2; s++) {
                const int ow  = ow0 + s;
                const int pix = oh * OHW + ow;
                #pragma unroll
                for (int b = 0; b < 2; b++) {
                    out[(b * 3 + 0) * OHW * OHW + pix] = rr[a][s][b][0];
                    out[(b * 3 + 1) * OHW * OHW + pix] = rr[a][s][b][1];
                    out[(b * 3 + 2) * OHW * OHW + pix] = rr[a][s][b][2];
                }
            }
        }
    }
}

extern "C" void kernel_launch(void* const* d_in, const int* in_sizes, int n_in,
                              void* d_out, int out_size)
{
    const float* x  = (const float*)d_in[0];   // (2,64,128,128) f32
    const float* lw = (const float*)d_in[1];   // (256,256,576,3) f32
    float* out = (float*)d_out;                // (2,3,256,256) f32

    meta_upscale_kernel<<<128 * 16, 256>>>(x, lw, out);
}